// round 14
// baseline (speedup 1.0000x reference)
#include <cuda_runtime.h>
#include <cuda_bf16.h>
#include <math.h>

// ---------------------------------------------------------------------------
// FrozenLSLModel == (pred, out_pos) lookup table (u <= 64 distinct preds).
// R11 = R10 (5 graph nodes) with shared-memory alignment fixed:
//   dec1v (dec_l1 grid + valid grid appended)
//   dec_l2
//   gemm1  (slot->p derived locally from g_pred via 64-bit distinct mask)
//   gemm2a (split-K gemm2 + last-block argmax, self-resetting counters)
//   out    (slot derived locally)
// All float4-accessed shared arrays are __align__(16); scalar shared ints
// are declared AFTER the arrays (R10's misaligned-address root cause).
// ---------------------------------------------------------------------------

#define HID 768
#define BITS 64
#define T_ROWS (BITS * BITS)

#define KSD 6                    // decoder l1 K-slices
#define KSLICED (HID / KSD)      // 128
#define KS1 12                   // gemm1 K-slices
#define KSLICE1 (HID / KS1)      // 64
#define KS2 8                    // gemm2 K-slices
#define KSLICE2 (HID / KS2)      // 96

__device__ float g_d1[KSD][BITS][HID];        // decoder l1 partials
__device__ float g_p1[KS1][T_ROWS][HID];      // gemm1 partials (slot-major)
__device__ float g_part[KS2][T_ROWS][BITS];   // gemm2 partials (slot-major)
__device__ float g_valid[T_ROWS];             // indexed by (p<<6)|i
__device__ int   g_idx[T_ROWS];               // indexed by (slot<<6)|i
__device__ int   g_pred[BITS];
__device__ int   g_cnt[T_ROWS / 32];          // gemm2a tickets (zero-init, self-reset)

// Build 64-bit mask of distinct pred values; all lanes of the warp get it.
__device__ __forceinline__ unsigned long long pred_mask_warp(int lane) {
    unsigned long long m = (1ull << g_pred[lane]) | (1ull << g_pred[lane + 32]);
    #pragma unroll
    for (int off = 16; off > 0; off >>= 1)
        m |= __shfl_xor_sync(0xffffffff, m, off);
    return m;
}

// ---------------------------------------------------------------------------
// K1: dec_l1 tasks (blocks 0..71) + valid tasks (blocks 72..583). 256 thr.
// ---------------------------------------------------------------------------
__global__ __launch_bounds__(256)
void dec1v_kernel(const float* __restrict__ Ws0, const float* __restrict__ bs0,
                  const float* __restrict__ Ws1,
                  const float* __restrict__ Wv0, const float* __restrict__ bv0,
                  const float* __restrict__ Wv1, const float* __restrict__ bv1) {
    int bid = blockIdx.x;
    int tid = threadIdx.x;

    if (bid < 72) {
        // ---- dec_l1: split-K GEMM, A built on the fly from Ws0 rows ----
        const int BK = 16;
        int n0 = (bid % 12) * 64;
        int k0 = (bid / 12) * KSLICED;

        __shared__ __align__(16) float As[BK][64];
        __shared__ __align__(16) float Bs[BK][64];

        int ty = tid >> 4, tx = tid & 15;
        int aRow = tid >> 2;          // s value 0..63
        int aK   = (tid & 3) * 4;
        int bRow = tid >> 4;
        int bCol = (tid & 15) * 4;

        float acc[4][4] = {};

        #pragma unroll 1
        for (int kt = 0; kt < KSLICED; kt += BK) {
            int gk = k0 + kt + aK;
            float4 v = *(const float4*)(bs0 + gk);
            #pragma unroll
            for (int b = 0; b < 6; b++) {
                if ((aRow >> b) & 1) {
                    float4 w = *(const float4*)(Ws0 + (size_t)b * HID + gk);
                    v.x += w.x; v.y += w.y; v.z += w.z; v.w += w.w;
                }
            }
            As[aK + 0][aRow] = fmaxf(v.x, 0.f);
            As[aK + 1][aRow] = fmaxf(v.y, 0.f);
            As[aK + 2][aRow] = fmaxf(v.z, 0.f);
            As[aK + 3][aRow] = fmaxf(v.w, 0.f);
            float4 bv = *(const float4*)(Ws1 + (size_t)(k0 + kt + bRow) * HID + n0 + bCol);
            *(float4*)&Bs[bRow][bCol] = bv;
            __syncthreads();

            #pragma unroll
            for (int k = 0; k < BK; k++) {
                float aF[4], bF[4];
                *(float4*)aF = *(const float4*)&As[k][ty * 4];
                *(float4*)bF = *(const float4*)&Bs[k][tx * 4];
                #pragma unroll
                for (int m = 0; m < 4; m++)
                    #pragma unroll
                    for (int n = 0; n < 4; n++)
                        acc[m][n] = fmaf(aF[m], bF[n], acc[m][n]);
            }
            __syncthreads();
        }

        #pragma unroll
        for (int m = 0; m < 4; m++) {
            float4 o;
            o.x = acc[m][0]; o.y = acc[m][1]; o.z = acc[m][2]; o.w = acc[m][3];
            *(float4*)&g_d1[bid / 12][ty * 4 + m][n0 + tx * 4] = o;
        }
    } else {
        // ---- valid: warp-per-row over all 4096 (p,i) rows ----
        int warp = tid >> 5;
        int lane = tid & 31;
        int t = (bid - 72) * 8 + warp;
        int p = t >> 6;
        int i = t & 63;

        const float* vp = Wv0 + (size_t)(BITS + p) * (HID / 2);
        const float* vi = Wv0 + (size_t)i * (HID / 2);
        float part = 0.f;
        #pragma unroll
        for (int r = 0; r < 12; r++) {
            int j = lane + r * 32;
            part += fmaxf(vp[j] + vi[j] + bv0[j], 0.f) * Wv1[j];
        }
        #pragma unroll
        for (int off = 16; off > 0; off >>= 1)
            part += __shfl_down_sync(0xffffffff, part, off);
        if (lane == 0) {
            float v = part + bv1[0];
            g_valid[t] = 1.f / (1.f + expf(-v));
        }
    }
}

// ---------------------------------------------------------------------------
// D2: decoder layer2 + argmax. One block per s.
// ---------------------------------------------------------------------------
__global__ __launch_bounds__(256)
void dec_l2_kernel(const float* __restrict__ bs1,
                   const float* __restrict__ Ws2, const float* __restrict__ bs2) {
    int s = blockIdx.x;
    int tid = threadIdx.x;
    __shared__ __align__(16) float h1[HID];
    __shared__ __align__(16) float part[4][BITS];
    __shared__ __align__(16) float lg[BITS];

    #pragma unroll
    for (int r = 0; r < 3; r++) {
        int j = tid + r * 256;
        float v = bs1[j];
        #pragma unroll
        for (int sl = 0; sl < KSD; sl++) v += g_d1[sl][s][j];
        h1[j] = fmaxf(v, 0.f);
    }
    __syncthreads();

    int col = tid & 63;
    int chunk = tid >> 6;                 // 0..3
    float p = 0.f;
    int kb = chunk * (HID / 4);
    for (int k = 0; k < HID / 4; k++)
        p = fmaf(h1[kb + k], Ws2[(size_t)(kb + k) * BITS + col], p);
    part[chunk][col] = p;
    __syncthreads();

    if (tid < BITS)
        lg[tid] = part[0][tid] + part[1][tid] + part[2][tid] + part[3][tid] + bs2[tid];
    __syncthreads();

    if (tid == 0) {
        float best = lg[0]; int bi = 0;
        for (int c = 1; c < BITS; c++)
            if (lg[c] > best) { best = lg[c]; bi = c; }
        g_pred[s] = bi;
    }
}

// ---------------------------------------------------------------------------
// G1: gemm1 split-K (R7 hot loop verbatim). slot->p derived locally.
// BM=64, BN=64, BK=16, KSLICE=64, 128 threads, 8x4 tile. grid (12, 64, 12).
// ---------------------------------------------------------------------------
__global__ __launch_bounds__(128)
void gemm1_kernel(const float* __restrict__ Wi0, const float* __restrict__ bi0,
                  const float* __restrict__ Wi1) {
    const int BK = 16, BM = 64, BN = 64;
    __shared__ __align__(16) float wpb[KSLICE1];
    __shared__ __align__(16) float As[2][BK][BM];
    __shared__ __align__(16) float Bs[2][BK][BN];
    __shared__ int s_p;

    int tid = threadIdx.x;
    int sl = blockIdx.y;

    if (tid < 32) {
        unsigned long long m = pred_mask_warp(tid);
        if (tid == 0) {
            int u = __popcll(m);
            int pv = -1;
            if (sl < u) {
                int cnt = 0;
                for (int q = 0; q < 64; q++)
                    if ((m >> q) & 1) { if (cnt == sl) { pv = q; break; } cnt++; }
            }
            s_p = pv;
        }
    }
    __syncthreads();
    int p = s_p;
    if (p < 0) return;

    int m0 = sl * BM;
    int n0 = blockIdx.x * BN;
    int k0 = blockIdx.z * KSLICE1;

    if (tid < KSLICE1)
        wpb[tid] = Wi0[(size_t)(BITS + p) * HID + k0 + tid] + bi0[k0 + tid];

    int aRow = tid >> 1;                   // 0..63 (= out_pos i)
    int aH   = (tid & 1) * 8;              // k-offset 0 or 8
    int bRow = tid >> 3;                   // 0..15
    int bCol = (tid & 7) * 8;              // 0..56
    int ty = tid >> 4, tx = tid & 15;      // 8x16 thread grid, 8x4 tile

    const float* WiRow = Wi0 + (size_t)aRow * HID + k0;
    const float* Bg = Wi1 + n0 + bCol;

    float acc[8][4] = {};
    __syncthreads();                       // wpb ready

    // prime buffer 0
    {
        float4 w0 = *(const float4*)(WiRow + aH);
        float4 w1 = *(const float4*)(WiRow + aH + 4);
        As[0][aH + 0][aRow] = fmaxf(w0.x + wpb[aH + 0], 0.f);
        As[0][aH + 1][aRow] = fmaxf(w0.y + wpb[aH + 1], 0.f);
        As[0][aH + 2][aRow] = fmaxf(w0.z + wpb[aH + 2], 0.f);
        As[0][aH + 3][aRow] = fmaxf(w0.w + wpb[aH + 3], 0.f);
        As[0][aH + 4][aRow] = fmaxf(w1.x + wpb[aH + 4], 0.f);
        As[0][aH + 5][aRow] = fmaxf(w1.y + wpb[aH + 5], 0.f);
        As[0][aH + 6][aRow] = fmaxf(w1.z + wpb[aH + 6], 0.f);
        As[0][aH + 7][aRow] = fmaxf(w1.w + wpb[aH + 7], 0.f);
        const float* br = Bg + (size_t)(k0 + bRow) * HID;
        float4 b0 = *(const float4*)(br);
        float4 b1 = *(const float4*)(br + 4);
        *(float4*)&Bs[0][bRow][bCol]     = b0;
        *(float4*)&Bs[0][bRow][bCol + 4] = b1;
    }
    __syncthreads();

    int cur = 0;
    #pragma unroll 1
    for (int kt = 0; kt < KSLICE1; kt += BK) {
        float4 w0, w1, b0, b1;
        bool more = (kt + BK) < KSLICE1;
        if (more) {
            int lk = kt + BK + aH;
            w0 = *(const float4*)(WiRow + lk);
            w1 = *(const float4*)(WiRow + lk + 4);
            const float* br = Bg + (size_t)(k0 + kt + BK + bRow) * HID;
            b0 = *(const float4*)(br);
            b1 = *(const float4*)(br + 4);
        }

        #pragma unroll
        for (int k = 0; k < BK; k++) {
            float aF[8], bF[4];
            *(float4*)&aF[0] = *(const float4*)&As[cur][k][ty * 8];
            *(float4*)&aF[4] = *(const float4*)&As[cur][k][ty * 8 + 4];
            *(float4*)bF = *(const float4*)&Bs[cur][k][tx * 4];
            #pragma unroll
            for (int m = 0; m < 8; m++)
                #pragma unroll
                for (int n = 0; n < 4; n++)
                    acc[m][n] = fmaf(aF[m], bF[n], acc[m][n]);
        }

        if (more) {
            int nxt = cur ^ 1;
            int lk = kt + BK + aH;
            As[nxt][aH + 0][aRow] = fmaxf(w0.x + wpb[lk + 0], 0.f);
            As[nxt][aH + 1][aRow] = fmaxf(w0.y + wpb[lk + 1], 0.f);
            As[nxt][aH + 2][aRow] = fmaxf(w0.z + wpb[lk + 2], 0.f);
            As[nxt][aH + 3][aRow] = fmaxf(w0.w + wpb[lk + 3], 0.f);
            As[nxt][aH + 4][aRow] = fmaxf(w1.x + wpb[lk + 4], 0.f);
            As[nxt][aH + 5][aRow] = fmaxf(w1.y + wpb[lk + 5], 0.f);
            As[nxt][aH + 6][aRow] = fmaxf(w1.z + wpb[lk + 6], 0.f);
            As[nxt][aH + 7][aRow] = fmaxf(w1.w + wpb[lk + 7], 0.f);
            *(float4*)&Bs[nxt][bRow][bCol]     = b0;
            *(float4*)&Bs[nxt][bRow][bCol + 4] = b1;
        }
        __syncthreads();
        cur ^= 1;
    }

    float* dst = &g_p1[blockIdx.z][m0 + ty * 8][n0 + tx * 4];
    #pragma unroll
    for (int m = 0; m < 8; m++) {
        float4 o;
        o.x = acc[m][0]; o.y = acc[m][1]; o.z = acc[m][2]; o.w = acc[m][3];
        *(float4*)(dst + (size_t)m * HID) = o;
    }
}

// ---------------------------------------------------------------------------
// G2a: gemm2 split-K (R7 hot loop verbatim) + last-block argmax.
// BM=32, BN=64, BK=16, grid (128, KS2). The 8th-finishing slice block for an
// m-tile runs warp-per-row argmax over the summed partials and resets the
// ticket counter (values deterministic regardless of which block reduces).
// ---------------------------------------------------------------------------
__global__ __launch_bounds__(256)
void gemm2a_kernel(const float* __restrict__ bi1, const float* __restrict__ Wi2,
                   const float* __restrict__ bi2) {
    const int BM = 32, BK = 16;
    __shared__ __align__(16) float As[BK][BM];
    __shared__ __align__(16) float Bs[BK][BITS];
    __shared__ int s_u;
    __shared__ int s_ticket;

    int tid = threadIdx.x;

    if (tid < 32) {
        unsigned long long m = pred_mask_warp(tid);
        if (tid == 0) s_u = __popcll(m);
    }
    __syncthreads();
    int m0 = blockIdx.x * BM;
    if (m0 >= s_u * BITS) return;
    int k0 = blockIdx.y * KSLICE2;

    int ty = tid >> 4, tx = tid & 15;
    int aRow = (tid >> 2) & 31;
    int aK   = (tid & 3) * 4;
    int bRow = tid >> 4;
    int bCol = (tid & 15) * 4;

    float acc[2][4] = {};

    #pragma unroll 1
    for (int kt = 0; kt < KSLICE2; kt += BK) {
        if (tid < 128) {
            int gk = k0 + kt + aK;
            int m = m0 + aRow;
            float4 s = *(const float4*)&g_p1[0][m][gk];
            #pragma unroll
            for (int sl = 1; sl < KS1; sl++) {
                float4 t = *(const float4*)&g_p1[sl][m][gk];
                s.x += t.x; s.y += t.y; s.z += t.z; s.w += t.w;
            }
            float4 b = *(const float4*)(bi1 + gk);
            As[aK + 0][aRow] = fmaxf(s.x + b.x, 0.f);
            As[aK + 1][aRow] = fmaxf(s.y + b.y, 0.f);
            As[aK + 2][aRow] = fmaxf(s.z + b.z, 0.f);
            As[aK + 3][aRow] = fmaxf(s.w + b.w, 0.f);
        }
        float4 bv = *(const float4*)(Wi2 + (size_t)(k0 + kt + bRow) * BITS + bCol);
        *(float4*)&Bs[bRow][bCol] = bv;
        __syncthreads();

        #pragma unroll
        for (int k = 0; k < BK; k++) {
            float aF[2], bF[4];
            aF[0] = As[k][ty * 2 + 0];
            aF[1] = As[k][ty * 2 + 1];
            *(float4*)bF = *(const float4*)&Bs[k][tx * 4];
            #pragma unroll
            for (int m = 0; m < 2; m++)
                #pragma unroll
                for (int n = 0; n < 4; n++)
                    acc[m][n] = fmaf(aF[m], bF[n], acc[m][n]);
        }
        __syncthreads();
    }

    #pragma unroll
    for (int m = 0; m < 2; m++) {
        float4 o;
        o.x = acc[m][0]; o.y = acc[m][1]; o.z = acc[m][2]; o.w = acc[m][3];
        *(float4*)&g_part[blockIdx.y][m0 + ty * 2 + m][tx * 4] = o;
    }

    // ---- last-block argmax over the 8 slices for this m-tile ----
    __syncthreads();
    __threadfence();
    if (tid == 0) s_ticket = atomicAdd(&g_cnt[blockIdx.x], 1);
    __syncthreads();
    if (s_ticket != KS2 - 1) return;
    __threadfence();

    int warp = tid >> 5;
    int lane = tid & 31;
    #pragma unroll
    for (int rr = 0; rr < 4; rr++) {
        int row = m0 + rr * 8 + warp;
        float v0 = bi2[lane];
        float v1 = bi2[lane + 32];
        #pragma unroll
        for (int s = 0; s < KS2; s++) {
            v0 += g_part[s][row][lane];
            v1 += g_part[s][row][lane + 32];
        }
        float best = v0; int bi = lane;
        if (v1 > best) { best = v1; bi = lane + 32; }
        #pragma unroll
        for (int off = 16; off > 0; off >>= 1) {
            float ob = __shfl_down_sync(0xffffffff, best, off);
            int   oi = __shfl_down_sync(0xffffffff, bi, off);
            if (ob > best || (ob == best && oi < bi)) { best = ob; bi = oi; }
        }
        if (lane == 0) g_idx[row] = bi;
    }
    if (tid == 0) g_cnt[blockIdx.x] = 0;   // self-reset for next replay
}

// ---------------------------------------------------------------------------
// out: warp per batch row; gather via shfl. slot derived locally from g_pred.
// ---------------------------------------------------------------------------
__global__ __launch_bounds__(256)
void out_kernel(const float* __restrict__ a_bits, const int* __restrict__ shift,
                float* __restrict__ out, int B) {
    int warp = threadIdx.x >> 5;
    int lane = threadIdx.x & 31;
    int b = blockIdx.x * 8 + warp;
    if (b >= B) return;

    unsigned long long mask = pred_mask_warp(lane);

    const float* arow = a_bits + ((size_t)b << 6);
    float a0 = arow[lane];
    float a1 = arow[lane + 32];
    int sv = shift[b];
    int p  = g_pred[sv];
    int sl = __popcll(mask & ((1ull << p) - 1ull));
    int tp = p << 6;
    int tb = sl << 6;

    int   i0 = g_idx[tb + lane];
    int   i1 = g_idx[tb + lane + 32];
    float v0 = g_valid[tp + lane];
    float v1 = g_valid[tp + lane + 32];

    float c00 = __shfl_sync(0xffffffff, a0, i0 & 31);
    float c01 = __shfl_sync(0xffffffff, a1, i0 & 31);
    float c10 = __shfl_sync(0xffffffff, a0, i1 & 31);
    float c11 = __shfl_sync(0xffffffff, a1, i1 & 31);

    float g0 = (i0 < 32) ? c00 : c01;
    float g1 = (i1 < 32) ? c10 : c11;

    out[((size_t)b << 6) + lane]      = g0 * v0;
    out[((size_t)b << 6) + lane + 32] = g1 * v1;
}

// ---------------------------------------------------------------------------
extern "C" void kernel_launch(void* const* d_in, const int* in_sizes, int n_in,
                              void* d_out, int out_size) {
    const float* a_bits = (const float*)d_in[0];
    const int*   shift  = (const int*)d_in[1];
    const float* Ws0 = (const float*)d_in[2];
    const float* bs0 = (const float*)d_in[3];
    const float* Ws1 = (const float*)d_in[4];
    const float* bs1 = (const float*)d_in[5];
    const float* Ws2 = (const float*)d_in[6];
    const float* bs2 = (const float*)d_in[7];
    const float* Wi0 = (const float*)d_in[8];
    const float* bi0 = (const float*)d_in[9];
    const float* Wi1 = (const float*)d_in[10];
    const float* bi1 = (const float*)d_in[11];
    const float* Wi2 = (const float*)d_in[12];
    const float* bi2 = (const float*)d_in[13];
    const float* Wv0 = (const float*)d_in[14];
    const float* bv0 = (const float*)d_in[15];
    const float* Wv1 = (const float*)d_in[16];
    const float* bv1 = (const float*)d_in[17];
    float* out = (float*)d_out;

    int B = in_sizes[1];               // 32768

    dec1v_kernel<<<72 + T_ROWS / 8, 256>>>(Ws0, bs0, Ws1, Wv0, bv0, Wv1, bv1);
    dec_l2_kernel<<<BITS, 256>>>(bs1, Ws2, bs2);

    dim3 g1(HID / 64, BITS, KS1);                  // (12, 64, 12)
    gemm1_kernel<<<g1, 128>>>(Wi0, bi0, Wi1);

    dim3 g2(T_ROWS / 32, KS2);                     // (128, 8)
    gemm2a_kernel<<<g2, 256>>>(bi1, Wi2, bi2);

    out_kernel<<<(B + 7) / 8, 256>>>(a_bits, shift, out, B);
}

// round 15
// speedup vs baseline: 1.0793x; 1.0793x over previous
#include <cuda_runtime.h>
#include <cuda_bf16.h>
#include <math.h>

// ---------------------------------------------------------------------------
// FrozenLSLModel == (pred, out_pos) lookup table (u <= 64 distinct preds).
// R15 = R7 verbatim with KS1 12 -> 6: halves the gemm1-partial traffic that
// gemm2's fused combine must read (measured 24.3us, DRAM-bound), while gemm1
// stays at its makespan sweet spot (720 active blocks, 4.9/SM).
// ---------------------------------------------------------------------------

#define HID 768
#define BITS 64
#define T_ROWS (BITS * BITS)

#define KSD 6                    // decoder l1 K-slices
#define KSLICED (HID / KSD)      // 128
#define KS1 6                    // gemm1 K-slices
#define KSLICE1 (HID / KS1)      // 128
#define KS2 8                    // gemm2 K-slices
#define KSLICE2 (HID / KS2)      // 96

__device__ float g_d1[KSD][BITS][HID];        // decoder l1 partials
__device__ float g_p1[KS1][T_ROWS][HID];      // gemm1 partials
__device__ float g_part[KS2][T_ROWS][BITS];   // gemm2 partials
__device__ float g_valid[T_ROWS];             // indexed by (p<<6)|i
__device__ int   g_idx[T_ROWS];               // indexed by (slot<<6)|i
__device__ int   g_pred[BITS];
__device__ int   g_u;
__device__ int   g_plist[BITS];
__device__ int   g_pred_slot[BITS];

// ---------------------------------------------------------------------------
// D1: decoder layer1 as split-K GEMM; A built on the fly from Ws0 rows.
// grid (12, KSD), 256 thr, BK=16.
// ---------------------------------------------------------------------------
__global__ __launch_bounds__(256)
void dec_l1_kernel(const float* __restrict__ Ws0, const float* __restrict__ bs0,
                   const float* __restrict__ Ws1) {
    const int BK = 16;
    int n0 = blockIdx.x * 64;
    int k0 = blockIdx.y * KSLICED;

    __shared__ __align__(16) float As[BK][64];
    __shared__ __align__(16) float Bs[BK][64];

    int tid = threadIdx.x;
    int ty = tid >> 4, tx = tid & 15;
    int aRow = tid >> 2;          // s value 0..63
    int aK   = (tid & 3) * 4;
    int bRow = tid >> 4;
    int bCol = (tid & 15) * 4;

    float acc[4][4] = {};

    #pragma unroll 1
    for (int kt = 0; kt < KSLICED; kt += BK) {
        int gk = k0 + kt + aK;
        float4 v = *(const float4*)(bs0 + gk);
        #pragma unroll
        for (int b = 0; b < 6; b++) {
            if ((aRow >> b) & 1) {
                float4 w = *(const float4*)(Ws0 + (size_t)b * HID + gk);
                v.x += w.x; v.y += w.y; v.z += w.z; v.w += w.w;
            }
        }
        As[aK + 0][aRow] = fmaxf(v.x, 0.f);
        As[aK + 1][aRow] = fmaxf(v.y, 0.f);
        As[aK + 2][aRow] = fmaxf(v.z, 0.f);
        As[aK + 3][aRow] = fmaxf(v.w, 0.f);
        float4 bv = *(const float4*)(Ws1 + (size_t)(k0 + kt + bRow) * HID + n0 + bCol);
        *(float4*)&Bs[bRow][bCol] = bv;
        __syncthreads();

        #pragma unroll
        for (int k = 0; k < BK; k++) {
            float aF[4], bF[4];
            *(float4*)aF = *(const float4*)&As[k][ty * 4];
            *(float4*)bF = *(const float4*)&Bs[k][tx * 4];
            #pragma unroll
            for (int m = 0; m < 4; m++)
                #pragma unroll
                for (int n = 0; n < 4; n++)
                    acc[m][n] = fmaf(aF[m], bF[n], acc[m][n]);
        }
        __syncthreads();
    }

    #pragma unroll
    for (int m = 0; m < 4; m++) {
        float4 o;
        o.x = acc[m][0]; o.y = acc[m][1]; o.z = acc[m][2]; o.w = acc[m][3];
        *(float4*)&g_d1[blockIdx.y][ty * 4 + m][n0 + tx * 4] = o;
    }
}

// ---------------------------------------------------------------------------
// D2: decoder layer2 + argmax. One block per s.
// ---------------------------------------------------------------------------
__global__ __launch_bounds__(256)
void dec_l2_kernel(const float* __restrict__ bs1,
                   const float* __restrict__ Ws2, const float* __restrict__ bs2) {
    int s = blockIdx.x;
    int tid = threadIdx.x;
    __shared__ __align__(16) float h1[HID];
    __shared__ __align__(16) float part[4][BITS];
    __shared__ __align__(16) float lg[BITS];

    #pragma unroll
    for (int r = 0; r < 3; r++) {
        int j = tid + r * 256;
        float v = bs1[j];
        #pragma unroll
        for (int sl = 0; sl < KSD; sl++) v += g_d1[sl][s][j];
        h1[j] = fmaxf(v, 0.f);
    }
    __syncthreads();

    int col = tid & 63;
    int chunk = tid >> 6;                 // 0..3
    float p = 0.f;
    int kb = chunk * (HID / 4);
    for (int k = 0; k < HID / 4; k++)
        p = fmaf(h1[kb + k], Ws2[(size_t)(kb + k) * BITS + col], p);
    part[chunk][col] = p;
    __syncthreads();

    if (tid < BITS)
        lg[tid] = part[0][tid] + part[1][tid] + part[2][tid] + part[3][tid] + bs2[tid];
    __syncthreads();

    if (tid == 0) {
        float best = lg[0]; int bi = 0;
        for (int c = 1; c < BITS; c++)
            if (lg[c] > best) { best = lg[c]; bi = c; }
        g_pred[s] = bi;
    }
}

// ---------------------------------------------------------------------------
// V: validity for ALL 4096 (p,i) rows, warp-per-row; block 0 compacts preds
// (runs after dec_l2 in single-stream order; zero extra nodes).
// ---------------------------------------------------------------------------
__global__ __launch_bounds__(256)
void valid_kernel(const float* __restrict__ Wv0, const float* __restrict__ bv0,
                  const float* __restrict__ Wv1, const float* __restrict__ bv1) {
    int warp = threadIdx.x >> 5;
    int lane = threadIdx.x & 31;
    int t = blockIdx.x * 8 + warp;
    int p = t >> 6;
    int i = t & 63;

    const float* vp = Wv0 + (size_t)(BITS + p) * (HID / 2);
    const float* vi = Wv0 + (size_t)i * (HID / 2);
    float part = 0.f;
    #pragma unroll
    for (int r = 0; r < 12; r++) {
        int j = lane + r * 32;
        part += fmaxf(vp[j] + vi[j] + bv0[j], 0.f) * Wv1[j];
    }
    #pragma unroll
    for (int off = 16; off > 0; off >>= 1)
        part += __shfl_down_sync(0xffffffff, part, off);
    if (lane == 0) {
        float v = part + bv1[0];
        g_valid[t] = 1.f / (1.f + expf(-v));
    }

    if (blockIdx.x == 0) {
        __shared__ int used[BITS];
        __shared__ int slot[BITS];
        int tid = threadIdx.x;
        if (tid < BITS) used[tid] = 0;
        __syncthreads();
        int pr = (tid < BITS) ? g_pred[tid] : 0;
        if (tid < BITS) used[pr] = 1;
        __syncthreads();
        if (tid == 0) {
            int u = 0;
            for (int q = 0; q < BITS; q++)
                if (used[q]) { g_plist[u] = q; slot[q] = u; u++; }
            g_u = u;
        }
        __syncthreads();
        if (tid < BITS) g_pred_slot[tid] = slot[pr];
    }
}

// ---------------------------------------------------------------------------
// G1: gemm1 split-K. BM=64, BN=64, BK=16, KSLICE=128, 128 threads, 8x4 tile.
// H1 fused into A-load; Wp+bi0 hoisted to wpb smem. grid (12, 64, 6).
// ---------------------------------------------------------------------------
__global__ __launch_bounds__(128)
void gemm1_kernel(const float* __restrict__ Wi0, const float* __restrict__ bi0,
                  const float* __restrict__ Wi1) {
    const int BK = 16, BM = 64, BN = 64;
    int sl = blockIdx.y;
    if (sl >= g_u) return;
    int p = g_plist[sl];
    int m0 = sl * BM;
    int n0 = blockIdx.x * BN;
    int k0 = blockIdx.z * KSLICE1;

    __shared__ __align__(16) float wpb[KSLICE1];
    __shared__ __align__(16) float As[2][BK][BM];
    __shared__ __align__(16) float Bs[2][BK][BN];

    int tid = threadIdx.x;
    if (tid < KSLICE1)
        wpb[tid] = Wi0[(size_t)(BITS + p) * HID + k0 + tid] + bi0[k0 + tid];

    int aRow = tid >> 1;                   // 0..63 (= out_pos i)
    int aH   = (tid & 1) * 8;              // k-offset 0 or 8
    int bRow = tid >> 3;                   // 0..15
    int bCol = (tid & 7) * 8;              // 0..56
    int ty = tid >> 4, tx = tid & 15;      // 8x16 thread grid, 8x4 tile

    const float* WiRow = Wi0 + (size_t)aRow * HID + k0;
    const float* Bg = Wi1 + n0 + bCol;

    float acc[8][4] = {};
    __syncthreads();                       // wpb ready

    // prime buffer 0
    {
        float4 w0 = *(const float4*)(WiRow + aH);
        float4 w1 = *(const float4*)(WiRow + aH + 4);
        As[0][aH + 0][aRow] = fmaxf(w0.x + wpb[aH + 0], 0.f);
        As[0][aH + 1][aRow] = fmaxf(w0.y + wpb[aH + 1], 0.f);
        As[0][aH + 2][aRow] = fmaxf(w0.z + wpb[aH + 2], 0.f);
        As[0][aH + 3][aRow] = fmaxf(w0.w + wpb[aH + 3], 0.f);
        As[0][aH + 4][aRow] = fmaxf(w1.x + wpb[aH + 4], 0.f);
        As[0][aH + 5][aRow] = fmaxf(w1.y + wpb[aH + 5], 0.f);
        As[0][aH + 6][aRow] = fmaxf(w1.z + wpb[aH + 6], 0.f);
        As[0][aH + 7][aRow] = fmaxf(w1.w + wpb[aH + 7], 0.f);
        const float* br = Bg + (size_t)(k0 + bRow) * HID;
        float4 b0 = *(const float4*)(br);
        float4 b1 = *(const float4*)(br + 4);
        *(float4*)&Bs[0][bRow][bCol]     = b0;
        *(float4*)&Bs[0][bRow][bCol + 4] = b1;
    }
    __syncthreads();

    int cur = 0;
    #pragma unroll 1
    for (int kt = 0; kt < KSLICE1; kt += BK) {
        float4 w0, w1, b0, b1;
        bool more = (kt + BK) < KSLICE1;
        if (more) {
            int lk = kt + BK + aH;
            w0 = *(const float4*)(WiRow + lk);
            w1 = *(const float4*)(WiRow + lk + 4);
            const float* br = Bg + (size_t)(k0 + kt + BK + bRow) * HID;
            b0 = *(const float4*)(br);
            b1 = *(const float4*)(br + 4);
        }

        #pragma unroll
        for (int k = 0; k < BK; k++) {
            float aF[8], bF[4];
            *(float4*)&aF[0] = *(const float4*)&As[cur][k][ty * 8];
            *(float4*)&aF[4] = *(const float4*)&As[cur][k][ty * 8 + 4];
            *(float4*)bF = *(const float4*)&Bs[cur][k][tx * 4];
            #pragma unroll
            for (int m = 0; m < 8; m++)
                #pragma unroll
                for (int n = 0; n < 4; n++)
                    acc[m][n] = fmaf(aF[m], bF[n], acc[m][n]);
        }

        if (more) {
            int nxt = cur ^ 1;
            int lk = kt + BK + aH;
            As[nxt][aH + 0][aRow] = fmaxf(w0.x + wpb[lk + 0], 0.f);
            As[nxt][aH + 1][aRow] = fmaxf(w0.y + wpb[lk + 1], 0.f);
            As[nxt][aH + 2][aRow] = fmaxf(w0.z + wpb[lk + 2], 0.f);
            As[nxt][aH + 3][aRow] = fmaxf(w0.w + wpb[lk + 3], 0.f);
            As[nxt][aH + 4][aRow] = fmaxf(w1.x + wpb[lk + 4], 0.f);
            As[nxt][aH + 5][aRow] = fmaxf(w1.y + wpb[lk + 5], 0.f);
            As[nxt][aH + 6][aRow] = fmaxf(w1.z + wpb[lk + 6], 0.f);
            As[nxt][aH + 7][aRow] = fmaxf(w1.w + wpb[lk + 7], 0.f);
            *(float4*)&Bs[nxt][bRow][bCol]     = b0;
            *(float4*)&Bs[nxt][bRow][bCol + 4] = b1;
        }
        __syncthreads();
        cur ^= 1;
    }

    float* dst = &g_p1[blockIdx.z][m0 + ty * 8][n0 + tx * 4];
    #pragma unroll
    for (int m = 0; m < 8; m++) {
        float4 o;
        o.x = acc[m][0]; o.y = acc[m][1]; o.z = acc[m][2]; o.w = acc[m][3];
        *(float4*)(dst + (size_t)m * HID) = o;
    }
}

// ---------------------------------------------------------------------------
// G2: gemm2 split-K; combine (sum KS1 partials + bias + relu) fused into
// A-load. BM=32, BN=64, BK=16, grid (128, KS2).
// ---------------------------------------------------------------------------
__global__ __launch_bounds__(256)
void gemm2_kernel(const float* __restrict__ bi1, const float* __restrict__ Wi2) {
    const int BM = 32, BK = 16;
    int m0 = blockIdx.x * BM;
    if (m0 >= g_u * BITS) return;
    int k0 = blockIdx.y * KSLICE2;

    __shared__ __align__(16) float As[BK][BM];
    __shared__ __align__(16) float Bs[BK][BITS];

    int tid = threadIdx.x;
    int ty = tid >> 4, tx = tid & 15;
    int aRow = (tid >> 2) & 31;
    int aK   = (tid & 3) * 4;
    int bRow = tid >> 4;
    int bCol = (tid & 15) * 4;

    float acc[2][4] = {};

    #pragma unroll 1
    for (int kt = 0; kt < KSLICE2; kt += BK) {
        if (tid < 128) {
            int gk = k0 + kt + aK;
            int m = m0 + aRow;
            float4 s = *(const float4*)&g_p1[0][m][gk];
            #pragma unroll
            for (int sl = 1; sl < KS1; sl++) {
                float4 t = *(const float4*)&g_p1[sl][m][gk];
                s.x += t.x; s.y += t.y; s.z += t.z; s.w += t.w;
            }
            float4 b = *(const float4*)(bi1 + gk);
            As[aK + 0][aRow] = fmaxf(s.x + b.x, 0.f);
            As[aK + 1][aRow] = fmaxf(s.y + b.y, 0.f);
            As[aK + 2][aRow] = fmaxf(s.z + b.z, 0.f);
            As[aK + 3][aRow] = fmaxf(s.w + b.w, 0.f);
        }
        float4 bv = *(const float4*)(Wi2 + (size_t)(k0 + kt + bRow) * BITS + bCol);
        *(float4*)&Bs[bRow][bCol] = bv;
        __syncthreads();

        #pragma unroll
        for (int k = 0; k < BK; k++) {
            float aF[2], bF[4];
            aF[0] = As[k][ty * 2 + 0];
            aF[1] = As[k][ty * 2 + 1];
            *(float4*)bF = *(const float4*)&Bs[k][tx * 4];
            #pragma unroll
            for (int m = 0; m < 2; m++)
                #pragma unroll
                for (int n = 0; n < 4; n++)
                    acc[m][n] = fmaf(aF[m], bF[n], acc[m][n]);
        }
        __syncthreads();
    }

    #pragma unroll
    for (int m = 0; m < 2; m++) {
        float4 o;
        o.x = acc[m][0]; o.y = acc[m][1]; o.z = acc[m][2]; o.w = acc[m][3];
        *(float4*)&g_part[blockIdx.y][m0 + ty * 2 + m][tx * 4] = o;
    }
}

// ---------------------------------------------------------------------------
// argmax over summed gemm2 partials. One warp per table row.
// ---------------------------------------------------------------------------
__global__ __launch_bounds__(256)
void argmax_kernel(const float* __restrict__ bi2) {
    int warp = threadIdx.x >> 5;
    int lane = threadIdx.x & 31;
    int row = blockIdx.x * 8 + warp;
    if (row >= g_u * BITS) return;

    float v0 = bi2[lane];
    float v1 = bi2[lane + 32];
    #pragma unroll
    for (int s = 0; s < KS2; s++) {
        v0 += g_part[s][row][lane];
        v1 += g_part[s][row][lane + 32];
    }
    float best = v0; int bi = lane;
    if (v1 > best) { best = v1; bi = lane + 32; }

    #pragma unroll
    for (int off = 16; off > 0; off >>= 1) {
        float ob = __shfl_down_sync(0xffffffff, best, off);
        int   oi = __shfl_down_sync(0xffffffff, bi, off);
        if (ob > best || (ob == best && oi < bi)) { best = ob; bi = oi; }
    }
    if (lane == 0) g_idx[row] = bi;
}

// ---------------------------------------------------------------------------
// out: warp per batch row; gather via shfl. valid indexed by p, idx by slot.
// ---------------------------------------------------------------------------
__global__ __launch_bounds__(256)
void out_kernel(const float* __restrict__ a_bits, const int* __restrict__ shift,
                float* __restrict__ out, int B) {
    int warp = threadIdx.x >> 5;
    int lane = threadIdx.x & 31;
    int b = blockIdx.x * 8 + warp;
    if (b >= B) return;

    const float* arow = a_bits + ((size_t)b << 6);
    float a0 = arow[lane];
    float a1 = arow[lane + 32];
    int sv = shift[b];
    int p  = g_pred[sv];
    int sl = g_pred_slot[sv];
    int tp = p << 6;
    int tb = sl << 6;

    int   i0 = g_idx[tb + lane];
    int   i1 = g_idx[tb + lane + 32];
    float v0 = g_valid[tp + lane];
    float v1 = g_valid[tp + lane + 32];

    float c00 = __shfl_sync(0xffffffff, a0, i0 & 31);
    float c01 = __shfl_sync(0xffffffff, a1, i0 & 31);
    float c10 = __shfl_sync(0xffffffff, a0, i1 & 31);
    float c11 = __shfl_sync(0xffffffff, a1, i1 & 31);

    float g0 = (i0 < 32) ? c00 : c01;
    float g1 = (i1 < 32) ? c10 : c11;

    out[((size_t)b << 6) + lane]      = g0 * v0;
    out[((size_t)b << 6) + lane + 32] = g1 * v1;
}

// ---------------------------------------------------------------------------
extern "C" void kernel_launch(void* const* d_in, const int* in_sizes, int n_in,
                              void* d_out, int out_size) {
    const float* a_bits = (const float*)d_in[0];
    const int*   shift  = (const int*)d_in[1];
    const float* Ws0 = (const float*)d_in[2];
    const float* bs0 = (const float*)d_in[3];
    const float* Ws1 = (const float*)d_in[4];
    const float* bs1 = (const float*)d_in[5];
    const float* Ws2 = (const float*)d_in[6];
    const float* bs2 = (const float*)d_in[7];
    const float* Wi0 = (const float*)d_in[8];
    const float* bi0 = (const float*)d_in[9];
    const float* Wi1 = (const float*)d_in[10];
    const float* bi1 = (const float*)d_in[11];
    const float* Wi2 = (const float*)d_in[12];
    const float* bi2 = (const float*)d_in[13];
    const float* Wv0 = (const float*)d_in[14];
    const float* bv0 = (const float*)d_in[15];
    const float* Wv1 = (const float*)d_in[16];
    const float* bv1 = (const float*)d_in[17];
    float* out = (float*)d_out;

    int B = in_sizes[1];               // 32768

    dim3 gd(HID / 64, KSD);                        // (12, 6)
    dec_l1_kernel<<<gd, 256>>>(Ws0, bs0, Ws1);
    dec_l2_kernel<<<BITS, 256>>>(bs1, Ws2, bs2);
    valid_kernel<<<T_ROWS / 8, 256>>>(Wv0, bv0, Wv1, bv1);

    dim3 g1(HID / 64, BITS, KS1);                  // (12, 64, 6)
    gemm1_kernel<<<g1, 128>>>(Wi0, bi0, Wi1);

    dim3 g2(T_ROWS / 32, KS2);                     // (128, 8)
    gemm2_kernel<<<g2, 256>>>(bi1, Wi2);
    argmax_kernel<<<T_ROWS / 8, 256>>>(bi2);

    out_kernel<<<(B + 7) / 8, 256>>>(a_bits, shift, out, B);
}